// round 6
// baseline (speedup 1.0000x reference)
#include <cuda_runtime.h>
#include <math.h>

#define NN 384
#define RR 128
#define KK 4
#define JJ 512   // K*R
#define GG 5
#define OO 2
#define TN 3     // nodes per k_social block

#define PI_OFF  0
#define MU_OFF  (NN*GG)              // 1920
#define SIG_OFF (MU_OFF + NN*GG*OO)  // 5760
#define H_OFF   (SIG_OFF + NN*GG*OO) // 9600
#define C_OFF   (H_OFF + NN*RR)      // 58752

// Scratch (no allocations allowed)
__device__ float g_P[KK*NN*RR];     // k-split: g_P[k][m][r]
__device__ float g_X[NN*RR];        // x = relu(nodes[:,:4]@W_in^T+b_in)+social
__device__ float g_WT[(256+8)*JJ];  // transposed [X|H] weights (+pad rows)
__device__ float g_G[NN*JJ];        // gate pre-activations
__device__ float g_Wmsum[KK];       // sum_r W_mode[r,k]
__device__ float g_bmsum[1];        // sum_r b_mode[r]

// ---------------------------------------------------------------------------
// K1: g_P[k][m][r] = dot6(W_loc[r*4+k], nodes[m]); 8 nodes per block.
// ---------------------------------------------------------------------------
__global__ void __launch_bounds__(512) k_pre(
    const float* __restrict__ nodes, const float* __restrict__ W_loc,
    const float* __restrict__ W_mode, const float* __restrict__ b_mode)
{
    int j = threadIdx.x;           // j' = k*128 + r
    int k = j >> 7, r = j & 127;
    int m0 = blockIdx.x * 8;
    __shared__ float nd[8][6];
    if (j < 48) nd[j/6][j%6] = nodes[m0*6 + j];
    const float* w = W_loc + (r*4 + k)*6;
    float w0 = w[0], w1 = w[1], w2 = w[2], w3 = w[3], w4 = w[4], w5 = w[5];
    __syncthreads();
    #pragma unroll
    for (int mm = 0; mm < 8; mm++) {
        g_P[k*(NN*RR) + (m0+mm)*RR + r] =
            w0*nd[mm][0] + w1*nd[mm][1] + w2*nd[mm][2]
          + w3*nd[mm][3] + w4*nd[mm][4] + w5*nd[mm][5];
    }

    if (blockIdx.x == 0 && j < 32) {
        float sk0=0.f, sk1=0.f, sk2=0.f, sk3=0.f, sbm=0.f;
        for (int rr = j; rr < RR; rr += 32) {
            sk0 += W_mode[rr*4+0];
            sk1 += W_mode[rr*4+1];
            sk2 += W_mode[rr*4+2];
            sk3 += W_mode[rr*4+3];
            sbm += b_mode[rr];
        }
        #pragma unroll
        for (int o = 16; o > 0; o >>= 1) {
            sk0 += __shfl_down_sync(0xffffffffu, sk0, o);
            sk1 += __shfl_down_sync(0xffffffffu, sk1, o);
            sk2 += __shfl_down_sync(0xffffffffu, sk2, o);
            sk3 += __shfl_down_sync(0xffffffffu, sk3, o);
            sbm += __shfl_down_sync(0xffffffffu, sbm, o);
        }
        if (j == 0) {
            g_Wmsum[0] = sk0; g_Wmsum[1] = sk1;
            g_Wmsum[2] = sk2; g_Wmsum[3] = sk3;
            g_bmsum[0] = sbm;
        }
    }
}

// ---------------------------------------------------------------------------
// K1b: transpose W_ih / W_hh into g_WT[k][j]  (k<128 -> W_ih, else W_hh).
// ---------------------------------------------------------------------------
__global__ void __launch_bounds__(256) k_wt(
    const float* __restrict__ W_ih, const float* __restrict__ W_hh)
{
    __shared__ float tile[32][33];
    int jb = blockIdx.x * 32;          // gridDim.x = 16
    int rb = blockIdx.y * 32;          // gridDim.y = 4
    const float* W = blockIdx.z ? W_hh : W_ih;
    int tx = threadIdx.x & 31;
    int ty = threadIdx.x >> 5;         // 0..7
    #pragma unroll
    for (int u = 0; u < 32; u += 8)
        tile[ty+u][tx] = W[(jb+ty+u)*RR + rb + tx];
    __syncthreads();
    int kbase = rb + blockIdx.z * RR;
    #pragma unroll
    for (int u = 0; u < 32; u += 8)
        g_WT[(kbase+ty+u)*JJ + jb + tx] = tile[tx][ty+u];
}

// ---------------------------------------------------------------------------
// K2: social attention, TN=3 nodes per block, 512 threads (128 blocks).
// ---------------------------------------------------------------------------
__global__ void __launch_bounds__(512) k_social(
    const float* __restrict__ nodes, const int* __restrict__ visible,
    const float* __restrict__ h_in,  const float* __restrict__ b_loc,
    const float* __restrict__ W_score, const float* __restrict__ b_score,
    const float* __restrict__ W_mode,  const float* __restrict__ b_mode,
    const float* __restrict__ W_in,    const float* __restrict__ b_in)
{
    int n0 = blockIdx.x * TN;
    int t = threadIdx.x;
    int lane = t & 31;
    int wrp  = t >> 5;                 // 0..15

    __shared__ __align__(16) float sPn[TN*KK*RR];   // [nn][k][r]
    __shared__ __align__(16) float sbk[KK*RR];      // [k][r]
    __shared__ __align__(16) float shs[TN*RR];      // [nn][r]
    __shared__ float ssv[TN][NN];
    __shared__ float sal[TN][NN];
    __shared__ int   skh[TN][NN];     // -1 => invisible
    __shared__ float scoef[TN][NN];   // w_i * alpha_i
    __shared__ float sred[16*5];
    __shared__ float sm4[TN][KK], sden[TN][KK], sSk[TN][KK];
    __shared__ float sWtot[TN];
    __shared__ float sscal[8];        // [0]=b_score, [1..4]=Wmsum, [5]=bmsum
    __shared__ float snd[TN][6];
    __shared__ float sCpart[3][TN][RR];

    // preamble
    for (int e = t; e < TN*KK*RR; e += 512) {
        int nn = e >> 9, k = (e >> 7) & 3, r = e & 127;
        sPn[e] = g_P[k*(NN*RR) + (n0+nn)*RR + r];
    }
    for (int e = t; e < KK*RR; e += 512) {
        int k = e >> 7, r = e & 127;
        sbk[e] = b_loc[r*4 + k];
    }
    if (t < TN*RR) shs[t] = h_in[n0*RR + t] * W_score[t & 127];
    if (t == 0) sscal[0] = b_score[0];
    if (t >= 32 && t < 36)  sscal[1 + (t-32)] = g_Wmsum[t-32];
    if (t == 36) sscal[5] = g_bmsum[0];
    if (t >= 64 && t < 64 + TN*6) { int e = t - 64; snd[e/6][e%6] = nodes[n0*6 + e]; }
    __syncthreads();

    // --- Phase A: 4 pairs per warp, 8 lanes per pair, 6 iterations ---
    {
        int p   = lane >> 3;   // pair within warp (0..3)
        int sub = lane & 7;    // lane within pair
        #pragma unroll 1
        for (int it = 0; it < 6; it++) {
            int i = it*64 + wrp*4 + p;
            float s[TN][KK], L[TN][KK];
            #pragma unroll
            for (int nn = 0; nn < TN; nn++)
                #pragma unroll
                for (int k = 0; k < KK; k++) { s[nn][k] = 0.f; L[nn][k] = 0.f; }

            #pragma unroll
            for (int k = 0; k < KK; k++) {
                const float4* Pik = (const float4*)(g_P + k*(NN*RR) + i*RR);
                const float4* Bk  = (const float4*)(sbk + k*RR);
                #pragma unroll
                for (int u = 0; u < 4; u++) {
                    int r4 = sub + 8*u;
                    float4 pi4 = Pik[r4];
                    float4 b4  = Bk[r4];
                    float bx = b4.x - pi4.x;
                    float by = b4.y - pi4.y;
                    float bz = b4.z - pi4.z;
                    float bw = b4.w - pi4.w;
                    #pragma unroll
                    for (int nn = 0; nn < TN; nn++) {
                        float4 pn4 = ((const float4*)(sPn + (nn*KK + k)*RR))[r4];
                        float4 h4  = ((const float4*)(shs + nn*RR))[r4];
                        float l0 = fmaxf(pn4.x + bx, 0.f);
                        float l1 = fmaxf(pn4.y + by, 0.f);
                        float l2 = fmaxf(pn4.z + bz, 0.f);
                        float l3 = fmaxf(pn4.w + bw, 0.f);
                        s[nn][k] += l0*h4.x + l1*h4.y + l2*h4.z + l3*h4.w;
                        L[nn][k] += (l0 + l1) + (l2 + l3);
                    }
                }
            }
            #pragma unroll
            for (int o = 4; o > 0; o >>= 1) {
                #pragma unroll
                for (int nn = 0; nn < TN; nn++)
                    #pragma unroll
                    for (int k = 0; k < KK; k++) {
                        s[nn][k] += __shfl_xor_sync(0xffffffffu, s[nn][k], o);
                        L[nn][k] += __shfl_xor_sync(0xffffffffu, L[nn][k], o);
                    }
            }
            if (sub == 0) {
                float bs = sscal[0];
                #pragma unroll
                for (int nn = 0; nn < TN; nn++) {
                    float s0 = s[nn][0]+bs, s1 = s[nn][1]+bs;
                    float s2 = s[nn][2]+bs, s3 = s[nn][3]+bs;
                    int kh = 0; float smx = s0;
                    if (s1 > smx) { smx = s1; kh = 1; }
                    if (s2 > smx) { smx = s2; kh = 2; }
                    if (s3 > smx) { smx = s3; kh = 3; }
                    float e0 = __expf(s0 - smx), e1 = __expf(s1 - smx);
                    float e2 = __expf(s2 - smx), e3 = __expf(s3 - smx);
                    float soft = 1.0f / (e0 + e1 + e2 + e3);   // softmax @khat
                    float alpha = (1.0f - soft) + soft;        // straight-through
                    float Lh = (kh==0) ? L[nn][0] : (kh==1) ? L[nn][1]
                             : (kh==2) ? L[nn][2] : L[nn][3];
                    float sv = alpha*Lh + (alpha*sscal[1+kh] + sscal[5]);
                    int vis = visible[(n0+nn)*NN + i];
                    skh[nn][i] = (vis > 0) ? kh : -1;
                    sal[nn][i] = alpha;
                    ssv[nn][i] = sv;
                }
            }
        }
    }
    __syncthreads();

    // --- Phase B: per-head masked softmax over neighbors, per node ---
    for (int nn = 0; nn < TN; nn++) {
        {   // pass 1: max per head
            float m0=-3.0e38f, m1=-3.0e38f, m2=-3.0e38f, m3=-3.0e38f;
            for (int i = t; i < NN; i += 512) {
                int kh = skh[nn][i];
                float v = ssv[nn][i];
                if (kh == 0) m0 = fmaxf(m0, v);
                else if (kh == 1) m1 = fmaxf(m1, v);
                else if (kh == 2) m2 = fmaxf(m2, v);
                else if (kh == 3) m3 = fmaxf(m3, v);
            }
            #pragma unroll
            for (int o = 16; o > 0; o >>= 1) {
                m0 = fmaxf(m0, __shfl_xor_sync(0xffffffffu, m0, o));
                m1 = fmaxf(m1, __shfl_xor_sync(0xffffffffu, m1, o));
                m2 = fmaxf(m2, __shfl_xor_sync(0xffffffffu, m2, o));
                m3 = fmaxf(m3, __shfl_xor_sync(0xffffffffu, m3, o));
            }
            if (lane == 0) {
                sred[wrp*4+0]=m0; sred[wrp*4+1]=m1;
                sred[wrp*4+2]=m2; sred[wrp*4+3]=m3;
            }
            __syncthreads();
            if (t < 4) {
                float m = sred[t];
                for (int ww = 1; ww < 16; ww++) m = fmaxf(m, sred[ww*4+t]);
                sm4[nn][t] = m;
            }
            __syncthreads();
        }
        {   // pass 2: denominators
            float d0=0.f, d1=0.f, d2=0.f, d3=0.f;
            for (int i = t; i < NN; i += 512) {
                int kh = skh[nn][i];
                if (kh >= 0) {
                    float e = __expf(ssv[nn][i] - sm4[nn][kh]);
                    if (kh == 0) d0 += e;
                    else if (kh == 1) d1 += e;
                    else if (kh == 2) d2 += e;
                    else d3 += e;
                }
            }
            #pragma unroll
            for (int o = 16; o > 0; o >>= 1) {
                d0 += __shfl_xor_sync(0xffffffffu, d0, o);
                d1 += __shfl_xor_sync(0xffffffffu, d1, o);
                d2 += __shfl_xor_sync(0xffffffffu, d2, o);
                d3 += __shfl_xor_sync(0xffffffffu, d3, o);
            }
            if (lane == 0) {
                sred[wrp*4+0]=d0; sred[wrp*4+1]=d1;
                sred[wrp*4+2]=d2; sred[wrp*4+3]=d3;
            }
            __syncthreads();
            if (t < 4) {
                float d = 0.f;
                for (int ww = 0; ww < 16; ww++) d += sred[ww*4+t];
                sden[nn][t] = d;
            }
            __syncthreads();
        }
        {   // pass 3: coefficients + group sums
            float k0=0.f, k1=0.f, k2=0.f, k3=0.f, wt=0.f;
            for (int i = t; i < NN; i += 512) {
                int kh = skh[nn][i];
                float c = 0.f;
                if (kh >= 0) {
                    float wv = __expf(ssv[nn][i] - sm4[nn][kh]) / sden[nn][kh];
                    c = wv * sal[nn][i];
                    wt += wv;
                    if (kh == 0) k0 += c;
                    else if (kh == 1) k1 += c;
                    else if (kh == 2) k2 += c;
                    else k3 += c;
                }
                scoef[nn][i] = c;
            }
            #pragma unroll
            for (int o = 16; o > 0; o >>= 1) {
                k0 += __shfl_xor_sync(0xffffffffu, k0, o);
                k1 += __shfl_xor_sync(0xffffffffu, k1, o);
                k2 += __shfl_xor_sync(0xffffffffu, k2, o);
                k3 += __shfl_xor_sync(0xffffffffu, k3, o);
                wt += __shfl_xor_sync(0xffffffffu, wt, o);
            }
            if (lane == 0) {
                sred[wrp*5+0]=k0; sred[wrp*5+1]=k1; sred[wrp*5+2]=k2;
                sred[wrp*5+3]=k3; sred[wrp*5+4]=wt;
            }
            __syncthreads();
            if (t < 5) {
                float s = 0.f;
                for (int ww = 0; ww < 16; ww++) s += sred[ww*5+t];
                if (t < 4) sSk[nn][t] = s; else sWtot[nn] = s;
            }
            __syncthreads();
        }
    }

    // --- Phase C: coalesced k-split accumulation, 4 quarters of i ---
    {
        int r = t & 127;
        int q = t >> 7;                 // 0..3
        float acc[TN];
        #pragma unroll
        for (int nn = 0; nn < TN; nn++) acc[nn] = 0.f;
        int i0 = q * 96;
        #pragma unroll 2
        for (int i = i0; i < i0 + 96; i++) {
            #pragma unroll
            for (int nn = 0; nn < TN; nn++) {
                int kh = skh[nn][i];
                float c = scoef[nn][i];
                if (kh >= 0 && c != 0.f) {
                    float pv = g_P[kh*(NN*RR) + i*RR + r];
                    acc[nn] += c * fmaxf(sPn[(nn*KK + kh)*RR + r] - pv
                                         + sbk[kh*RR + r], 0.f);
                }
            }
        }
        if (q) {
            #pragma unroll
            for (int nn = 0; nn < TN; nn++) sCpart[q-1][nn][r] = acc[nn];
        }
        __syncthreads();
        if (q == 0) {
            float wm0 = W_mode[r*4+0], wm1 = W_mode[r*4+1];
            float wm2 = W_mode[r*4+2], wm3 = W_mode[r*4+3];
            float bm = b_mode[r];
            const float* wi = W_in + r*4;
            float wi0 = wi[0], wi1 = wi[1], wi2 = wi[2], wi3 = wi[3];
            float bi = b_in[r];
            #pragma unroll
            for (int nn = 0; nn < TN; nn++) {
                float a = acc[nn] + sCpart[0][nn][r] + sCpart[1][nn][r]
                        + sCpart[2][nn][r];
                float soc = a + sSk[nn][0]*wm0 + sSk[nn][1]*wm1
                              + sSk[nn][2]*wm2 + sSk[nn][3]*wm3
                              + sWtot[nn]*bm;
                float xr = fmaxf(wi0*snd[nn][0] + wi1*snd[nn][1]
                               + wi2*snd[nn][2] + wi3*snd[nn][3] + bi, 0.f)
                         + soc;
                g_X[(n0+nn)*RR + r] = xr;
            }
        }
    }
}

// ---------------------------------------------------------------------------
// K3a: gates GEMM. grid (16 j-tiles, 12 node-tiles), 256 threads.
// g_G[n][j] = [X|H][n] . WT[:][j] + b_ih[j] + b_hh[j]
// ---------------------------------------------------------------------------
__global__ void __launch_bounds__(256) k_gates(
    const float* __restrict__ h_in,
    const float* __restrict__ b_ih, const float* __restrict__ b_hh)
{
    int jt = blockIdx.x;   // 0..15 -> j tile of 32
    int mt = blockIdx.y;   // 0..11 -> node tile of 32
    int t = threadIdx.x;
    int jl = t & 31;
    int ng = t >> 5;       // 0..7: nodes ng*4 .. ng*4+3 within tile

    __shared__ __align__(16) float sA[32][256];   // [node][k]

    for (int e = t; e < 32*256; e += 256) {
        int n = e >> 8, k = e & 255;
        sA[n][k] = (k < 128) ? g_X[(mt*32+n)*RR + k]
                             : h_in[(mt*32+n)*RR + (k-128)];
    }
    __syncthreads();

    int j = jt*32 + jl;
    const float* Wcol = g_WT + j;
    float acc0 = 0.f, acc1 = 0.f, acc2 = 0.f, acc3 = 0.f;
    int nb = ng*4;

    float wb[8];
    #pragma unroll
    for (int u = 0; u < 8; u++) wb[u] = Wcol[u*JJ];
    #pragma unroll 1
    for (int kt = 0; kt < 256; kt += 8) {
        float wn[8];
        #pragma unroll
        for (int u = 0; u < 8; u++) wn[u] = Wcol[(kt+8+u)*JJ];  // padded rows
        #pragma unroll
        for (int u = 0; u < 8; u += 4) {
            float4 a0 = *(const float4*)&sA[nb+0][kt+u];
            float4 a1 = *(const float4*)&sA[nb+1][kt+u];
            float4 a2 = *(const float4*)&sA[nb+2][kt+u];
            float4 a3 = *(const float4*)&sA[nb+3][kt+u];
            float w0 = wb[u], w1 = wb[u+1], w2 = wb[u+2], w3 = wb[u+3];
            acc0 += a0.x*w0 + a0.y*w1 + a0.z*w2 + a0.w*w3;
            acc1 += a1.x*w0 + a1.y*w1 + a1.z*w2 + a1.w*w3;
            acc2 += a2.x*w0 + a2.y*w1 + a2.z*w2 + a2.w*w3;
            acc3 += a3.x*w0 + a3.y*w1 + a3.z*w2 + a3.w*w3;
        }
        #pragma unroll
        for (int u = 0; u < 8; u++) wb[u] = wn[u];
    }
    float bb = b_ih[j] + b_hh[j];
    int nbase = mt*32 + nb;
    g_G[(nbase+0)*JJ + j] = acc0 + bb;
    g_G[(nbase+1)*JJ + j] = acc1 + bb;
    g_G[(nbase+2)*JJ + j] = acc2 + bb;
    g_G[(nbase+3)*JJ + j] = acc3 + bb;
}

// ---------------------------------------------------------------------------
// K3b: LSTM pointwise combine + MDN heads. 8 nodes/block, 48 blocks.
// ---------------------------------------------------------------------------
__device__ __forceinline__ float sigf(float x) { return 1.f / (1.f + __expf(-x)); }

#define BN 8
__global__ void __launch_bounds__(256) k_comb(
    const float* __restrict__ c_in,
    const float* __restrict__ W_pi, const float* __restrict__ b_pi,
    const float* __restrict__ W_mu, const float* __restrict__ b_mu,
    const float* __restrict__ W_sig, const float* __restrict__ b_sig,
    float* __restrict__ out)
{
    int n0 = blockIdx.x * BN;
    int t = threadIdx.x;

    __shared__ float sW[25*RR];
    __shared__ float sh[BN][RR];
    __shared__ float sLg[BN][25];

    for (int e = t; e < 25*RR; e += 256) {
        float v = (e < 640) ? W_pi[e] : (e < 1920) ? W_mu[e-640] : W_sig[e-1920];
        sW[e] = v;
    }

    for (int e = t; e < BN*RR; e += 256) {
        int nn = e >> 7, r = e & 127;
        int n = n0 + nn;
        float gi = g_G[n*JJ + r];
        float gf = g_G[n*JJ + RR + r];
        float gg = g_G[n*JJ + 2*RR + r];
        float go = g_G[n*JJ + 3*RR + r];
        float cp = c_in[n*RR + r];
        float c = sigf(gf)*cp + sigf(gi)*tanhf(gg);
        float h = sigf(go)*tanhf(c);
        out[C_OFF + n*RR + r] = c;
        out[H_OFF + n*RR + r] = h;
        sh[nn][r] = h;
    }
    __syncthreads();

    // heads: 25 dot products per node
    if (t < BN*25) {
        int nn = t / 25, q = t % 25;
        const float* wr = sW + q*RR;
        float acc = 0.f;
        #pragma unroll 4
        for (int r = 0; r < RR; r++) acc += wr[r] * sh[nn][r];
        sLg[nn][q] = acc;
    }
    __syncthreads();

    if (t < BN) {  // pi softmax
        int nn = t;
        float l[GG];
        float m = -3.0e38f;
        #pragma unroll
        for (int g = 0; g < GG; g++) { l[g] = sLg[nn][g] + b_pi[g]; m = fmaxf(m, l[g]); }
        float s = 0.f;
        #pragma unroll
        for (int g = 0; g < GG; g++) { l[g] = __expf(l[g] - m); s += l[g]; }
        float inv = 1.f / s;
        #pragma unroll
        for (int g = 0; g < GG; g++)
            out[PI_OFF + (n0+nn)*GG + g] = l[g] * inv;
    }
    if (t >= 32 && t < 32 + BN*10) {  // mu
        int idx = t - 32;
        int nn = idx / 10, q = idx % 10;
        out[MU_OFF + (n0+nn)*10 + q] = sLg[nn][5+q] + b_mu[q];
    }
    if (t >= 128 && t < 128 + BN*10) {  // sigma
        int idx = t - 128;
        int nn = idx / 10, q = idx % 10;
        out[SIG_OFF + (n0+nn)*10 + q] = __expf(sLg[nn][15+q] + b_sig[q]);
    }
}

// ---------------------------------------------------------------------------
extern "C" void kernel_launch(void* const* d_in, const int* in_sizes, int n_in,
                              void* d_out, int out_size)
{
    const float* nodes   = (const float*)d_in[0];
    const int*   visible = (const int*)  d_in[1];
    const float* h_in    = (const float*)d_in[2];
    const float* c_in    = (const float*)d_in[3];
    const float* W_loc   = (const float*)d_in[4];
    const float* b_loc   = (const float*)d_in[5];
    const float* W_score = (const float*)d_in[6];
    const float* b_score = (const float*)d_in[7];
    const float* W_mode  = (const float*)d_in[8];
    const float* b_mode  = (const float*)d_in[9];
    const float* W_in    = (const float*)d_in[10];
    const float* b_in    = (const float*)d_in[11];
    const float* W_ih    = (const float*)d_in[12];
    const float* W_hh    = (const float*)d_in[13];
    const float* b_ih    = (const float*)d_in[14];
    const float* b_hh    = (const float*)d_in[15];
    const float* W_pi    = (const float*)d_in[16];
    const float* b_pi    = (const float*)d_in[17];
    const float* W_mu    = (const float*)d_in[18];
    const float* b_mu    = (const float*)d_in[19];
    const float* W_sig   = (const float*)d_in[20];
    const float* b_sig   = (const float*)d_in[21];
    float* out = (float*)d_out;

    k_pre<<<NN/8, 512>>>(nodes, W_loc, W_mode, b_mode);
    dim3 wt_grid(16, 4, 2);
    k_wt<<<wt_grid, 256>>>(W_ih, W_hh);
    k_social<<<NN/TN, 512>>>(nodes, visible, h_in, b_loc, W_score, b_score,
                             W_mode, b_mode, W_in, b_in);
    dim3 g_grid(16, 12);
    k_gates<<<g_grid, 256>>>(h_in, b_ih, b_hh);
    k_comb<<<NN/BN, 256>>>(c_in, W_pi, b_pi, W_mu, b_mu, W_sig, b_sig, out);
}

// round 7
// speedup vs baseline: 1.5078x; 1.5078x over previous
#include <cuda_runtime.h>
#include <math.h>

#define NN 384
#define RR 128
#define KK 4
#define JJ 512   // K*R
#define GG 5
#define OO 2
#define TN 3     // nodes per social block

#define PI_OFF  0
#define MU_OFF  (NN*GG)              // 1920
#define SIG_OFF (MU_OFF + NN*GG*OO)  // 5760
#define H_OFF   (SIG_OFF + NN*GG*OO) // 9600
#define C_OFF   (H_OFF + NN*RR)      // 58752

// Scratch (no allocations allowed)
__device__ float g_Pj[NN*JJ];       // interleaved: P[m][j]
__device__ float g_Pk[KK*NN*RR];    // k-split:     P[k][m][r]
__device__ float g_X[NN*RR];
__device__ float g_WT[(256+8)*JJ];  // transposed [X|H] weights
__device__ float g_G[NN*JJ];        // gate pre-activations
__device__ float g_sv[NN*NN];       // phase-A outputs
__device__ float g_al[NN*NN];
__device__ int   g_kh[NN*NN];
__device__ float g_Wmsum[KK];
__device__ float g_bmsum[1];

// ---------------------------------------------------------------------------
// K1: P in both layouts. 8 nodes per block; block 0 reduces W_mode sums.
// ---------------------------------------------------------------------------
__global__ void __launch_bounds__(512) k_pre(
    const float* __restrict__ nodes, const float* __restrict__ W_loc,
    const float* __restrict__ W_mode, const float* __restrict__ b_mode)
{
    int j = threadIdx.x;            // W_loc row j ; r = j>>2, k = j&3
    int m0 = blockIdx.x * 8;
    __shared__ float nd[8][6];
    if (j < 48) nd[j/6][j%6] = nodes[m0*6 + j];
    const float* w = W_loc + j*6;
    float w0 = w[0], w1 = w[1], w2 = w[2], w3 = w[3], w4 = w[4], w5 = w[5];
    int k = j & 3, r = j >> 2;
    __syncthreads();
    #pragma unroll
    for (int mm = 0; mm < 8; mm++) {
        float v = w0*nd[mm][0] + w1*nd[mm][1] + w2*nd[mm][2]
                + w3*nd[mm][3] + w4*nd[mm][4] + w5*nd[mm][5];
        g_Pj[(m0+mm)*JJ + j] = v;
        g_Pk[k*(NN*RR) + (m0+mm)*RR + r] = v;
    }

    if (blockIdx.x == 0 && j < 32) {
        float sk0=0.f, sk1=0.f, sk2=0.f, sk3=0.f, sbm=0.f;
        for (int rr = j; rr < RR; rr += 32) {
            sk0 += W_mode[rr*4+0];
            sk1 += W_mode[rr*4+1];
            sk2 += W_mode[rr*4+2];
            sk3 += W_mode[rr*4+3];
            sbm += b_mode[rr];
        }
        #pragma unroll
        for (int o = 16; o > 0; o >>= 1) {
            sk0 += __shfl_down_sync(0xffffffffu, sk0, o);
            sk1 += __shfl_down_sync(0xffffffffu, sk1, o);
            sk2 += __shfl_down_sync(0xffffffffu, sk2, o);
            sk3 += __shfl_down_sync(0xffffffffu, sk3, o);
            sbm += __shfl_down_sync(0xffffffffu, sbm, o);
        }
        if (j == 0) {
            g_Wmsum[0] = sk0; g_Wmsum[1] = sk1;
            g_Wmsum[2] = sk2; g_Wmsum[3] = sk3;
            g_bmsum[0] = sbm;
        }
    }
}

// ---------------------------------------------------------------------------
// K1b: transpose W_ih / W_hh into g_WT[k][j]  (k<128 -> W_ih, else W_hh).
// ---------------------------------------------------------------------------
__global__ void __launch_bounds__(256) k_wt(
    const float* __restrict__ W_ih, const float* __restrict__ W_hh)
{
    __shared__ float tile[32][33];
    int jb = blockIdx.x * 32;          // gridDim.x = 16
    int rb = blockIdx.y * 32;          // gridDim.y = 4
    const float* W = blockIdx.z ? W_hh : W_ih;
    int tx = threadIdx.x & 31;
    int ty = threadIdx.x >> 5;         // 0..7
    #pragma unroll
    for (int u = 0; u < 32; u += 8)
        tile[ty+u][tx] = W[(jb+ty+u)*RR + rb + tx];
    __syncthreads();
    int kbase = rb + blockIdx.z * RR;
    #pragma unroll
    for (int u = 0; u < 32; u += 8)
        g_WT[(kbase+ty+u)*JJ + jb + tx] = tile[tx][ty+u];
}

// ---------------------------------------------------------------------------
// K2a: Phase A — per-pair scores. grid (128 n-tiles, 4 i-tiles), 256 thr.
// ---------------------------------------------------------------------------
__global__ void __launch_bounds__(256) k_socialA(
    const int* __restrict__ visible, const float* __restrict__ h_in,
    const float* __restrict__ b_loc, const float* __restrict__ W_score,
    const float* __restrict__ b_score)
{
    int n0 = blockIdx.x * TN;
    int ib = blockIdx.y * 96;
    int t = threadIdx.x;
    int lane = t & 31;
    int wrp  = t >> 5;

    __shared__ __align__(16) float sPn[TN*JJ];
    __shared__ __align__(16) float sb[JJ];
    __shared__ float shs[TN*RR];
    __shared__ float sscal[8];

    for (int e = t; e < TN*JJ; e += 256) sPn[e] = g_Pj[n0*JJ + e];
    for (int e = t; e < JJ; e += 256)    sb[e] = b_loc[e];
    for (int e = t; e < TN*RR; e += 256)
        shs[e] = h_in[n0*RR + e] * W_score[e & 127];
    if (t == 0) sscal[0] = b_score[0];
    if (t >= 32 && t < 36) sscal[1 + (t-32)] = g_Wmsum[t-32];
    if (t == 36) sscal[5] = g_bmsum[0];
    __syncthreads();

    int p   = lane >> 3;   // pair within warp (0..3)
    int sub = lane & 7;    // lane within pair
    const float4* B4 = (const float4*)sb;
    #pragma unroll 1
    for (int pass = 0; pass < 3; pass++) {
        int i = ib + pass*32 + wrp*4 + p;
        const float4* Pi = (const float4*)(g_Pj + i*JJ);
        float s[TN][4], L[TN][4];
        #pragma unroll
        for (int nn = 0; nn < TN; nn++)
            #pragma unroll
            for (int kk = 0; kk < 4; kk++) { s[nn][kk] = 0.f; L[nn][kk] = 0.f; }

        #pragma unroll
        for (int u = 0; u < 16; u++) {
            int r = sub + 8*u;
            float4 pi4 = Pi[r];
            float4 b4  = B4[r];
            float bx = b4.x - pi4.x;
            float by = b4.y - pi4.y;
            float bz = b4.z - pi4.z;
            float bw = b4.w - pi4.w;
            #pragma unroll
            for (int nn = 0; nn < TN; nn++) {
                float4 pn4 = ((const float4*)(sPn + nn*JJ))[r];
                float hv = shs[nn*RR + r];
                float l0 = fmaxf(pn4.x + bx, 0.f);
                float l1 = fmaxf(pn4.y + by, 0.f);
                float l2 = fmaxf(pn4.z + bz, 0.f);
                float l3 = fmaxf(pn4.w + bw, 0.f);
                s[nn][0] += l0*hv; s[nn][1] += l1*hv;
                s[nn][2] += l2*hv; s[nn][3] += l3*hv;
                L[nn][0] += l0; L[nn][1] += l1;
                L[nn][2] += l2; L[nn][3] += l3;
            }
        }
        #pragma unroll
        for (int o = 4; o > 0; o >>= 1) {
            #pragma unroll
            for (int nn = 0; nn < TN; nn++)
                #pragma unroll
                for (int kk = 0; kk < 4; kk++) {
                    s[nn][kk] += __shfl_xor_sync(0xffffffffu, s[nn][kk], o);
                    L[nn][kk] += __shfl_xor_sync(0xffffffffu, L[nn][kk], o);
                }
        }
        if (sub == 0) {
            float bs = sscal[0];
            #pragma unroll
            for (int nn = 0; nn < TN; nn++) {
                float s0 = s[nn][0]+bs, s1 = s[nn][1]+bs;
                float s2 = s[nn][2]+bs, s3 = s[nn][3]+bs;
                int kh = 0; float smx = s0;
                if (s1 > smx) { smx = s1; kh = 1; }
                if (s2 > smx) { smx = s2; kh = 2; }
                if (s3 > smx) { smx = s3; kh = 3; }
                float e0 = __expf(s0 - smx), e1 = __expf(s1 - smx);
                float e2 = __expf(s2 - smx), e3 = __expf(s3 - smx);
                float soft = 1.0f / (e0 + e1 + e2 + e3);   // softmax @khat
                float alpha = (1.0f - soft) + soft;        // straight-through
                float Lh = (kh==0) ? L[nn][0] : (kh==1) ? L[nn][1]
                         : (kh==2) ? L[nn][2] : L[nn][3];
                float sv = alpha*Lh + (alpha*sscal[1+kh] + sscal[5]);
                int vis = visible[(n0+nn)*NN + i];
                int idx = (n0+nn)*NN + i;
                g_kh[idx] = (vis > 0) ? kh : -1;
                g_al[idx] = alpha;
                g_sv[idx] = sv;
            }
        }
    }
}

// ---------------------------------------------------------------------------
// K2b: Phase B (masked softmax) + Phase C (accumulation). 128 blocks, 512 thr.
// ---------------------------------------------------------------------------
__global__ void __launch_bounds__(512) k_socialBC(
    const float* __restrict__ nodes, const float* __restrict__ b_loc,
    const float* __restrict__ W_mode, const float* __restrict__ b_mode,
    const float* __restrict__ W_in,   const float* __restrict__ b_in)
{
    int n0 = blockIdx.x * TN;
    int t = threadIdx.x;
    int lane = t & 31;
    int wrp  = t >> 5;                 // 0..15

    __shared__ __align__(16) float sPn[TN*KK*RR];   // [nn][k][r] (k-split)
    __shared__ __align__(16) float sbk[KK*RR];      // [k][r]
    __shared__ float ssv[TN][NN];
    __shared__ float sal[TN][NN];
    __shared__ int   skh[TN][NN];
    __shared__ float scoef[TN][NN];
    __shared__ float sred[16*5];
    __shared__ float sm4[TN][KK], sden[TN][KK], sSk[TN][KK];
    __shared__ float sWtot[TN];
    __shared__ float snd[TN][6];
    __shared__ float sCpart[3][TN][RR];

    for (int e = t; e < TN*KK*RR; e += 512) {
        int nn = e >> 9, k = (e >> 7) & 3, r = e & 127;
        sPn[e] = g_Pk[k*(NN*RR) + (n0+nn)*RR + r];
    }
    for (int e = t; e < KK*RR; e += 512) {
        int k = e >> 7, r = e & 127;
        sbk[e] = b_loc[r*4 + k];
    }
    for (int e = t; e < TN*NN; e += 512) {
        ((float*)ssv)[e] = g_sv[n0*NN + e];
        ((float*)sal)[e] = g_al[n0*NN + e];
        ((int*)skh)[e]   = g_kh[n0*NN + e];
    }
    if (t < TN*6) snd[t/6][t%6] = nodes[n0*6 + t];
    __syncthreads();

    // --- Phase B: per-head masked softmax over neighbors, per node ---
    for (int nn = 0; nn < TN; nn++) {
        {   // pass 1: max per head
            float m0=-3.0e38f, m1=-3.0e38f, m2=-3.0e38f, m3=-3.0e38f;
            for (int i = t; i < NN; i += 512) {
                int kh = skh[nn][i];
                float v = ssv[nn][i];
                if (kh == 0) m0 = fmaxf(m0, v);
                else if (kh == 1) m1 = fmaxf(m1, v);
                else if (kh == 2) m2 = fmaxf(m2, v);
                else if (kh == 3) m3 = fmaxf(m3, v);
            }
            #pragma unroll
            for (int o = 16; o > 0; o >>= 1) {
                m0 = fmaxf(m0, __shfl_xor_sync(0xffffffffu, m0, o));
                m1 = fmaxf(m1, __shfl_xor_sync(0xffffffffu, m1, o));
                m2 = fmaxf(m2, __shfl_xor_sync(0xffffffffu, m2, o));
                m3 = fmaxf(m3, __shfl_xor_sync(0xffffffffu, m3, o));
            }
            if (lane == 0) {
                sred[wrp*4+0]=m0; sred[wrp*4+1]=m1;
                sred[wrp*4+2]=m2; sred[wrp*4+3]=m3;
            }
            __syncthreads();
            if (t < 4) {
                float m = sred[t];
                for (int ww = 1; ww < 16; ww++) m = fmaxf(m, sred[ww*4+t]);
                sm4[nn][t] = m;
            }
            __syncthreads();
        }
        {   // pass 2: denominators
            float d0=0.f, d1=0.f, d2=0.f, d3=0.f;
            for (int i = t; i < NN; i += 512) {
                int kh = skh[nn][i];
                if (kh >= 0) {
                    float e = __expf(ssv[nn][i] - sm4[nn][kh]);
                    if (kh == 0) d0 += e;
                    else if (kh == 1) d1 += e;
                    else if (kh == 2) d2 += e;
                    else d3 += e;
                }
            }
            #pragma unroll
            for (int o = 16; o > 0; o >>= 1) {
                d0 += __shfl_xor_sync(0xffffffffu, d0, o);
                d1 += __shfl_xor_sync(0xffffffffu, d1, o);
                d2 += __shfl_xor_sync(0xffffffffu, d2, o);
                d3 += __shfl_xor_sync(0xffffffffu, d3, o);
            }
            if (lane == 0) {
                sred[wrp*4+0]=d0; sred[wrp*4+1]=d1;
                sred[wrp*4+2]=d2; sred[wrp*4+3]=d3;
            }
            __syncthreads();
            if (t < 4) {
                float d = 0.f;
                for (int ww = 0; ww < 16; ww++) d += sred[ww*4+t];
                sden[nn][t] = d;
            }
            __syncthreads();
        }
        {   // pass 3: coefficients + group sums
            float k0=0.f, k1=0.f, k2=0.f, k3=0.f, wt=0.f;
            for (int i = t; i < NN; i += 512) {
                int kh = skh[nn][i];
                float c = 0.f;
                if (kh >= 0) {
                    float wv = __expf(ssv[nn][i] - sm4[nn][kh]) / sden[nn][kh];
                    c = wv * sal[nn][i];
                    wt += wv;
                    if (kh == 0) k0 += c;
                    else if (kh == 1) k1 += c;
                    else if (kh == 2) k2 += c;
                    else k3 += c;
                }
                scoef[nn][i] = c;
            }
            #pragma unroll
            for (int o = 16; o > 0; o >>= 1) {
                k0 += __shfl_xor_sync(0xffffffffu, k0, o);
                k1 += __shfl_xor_sync(0xffffffffu, k1, o);
                k2 += __shfl_xor_sync(0xffffffffu, k2, o);
                k3 += __shfl_xor_sync(0xffffffffu, k3, o);
                wt += __shfl_xor_sync(0xffffffffu, wt, o);
            }
            if (lane == 0) {
                sred[wrp*5+0]=k0; sred[wrp*5+1]=k1; sred[wrp*5+2]=k2;
                sred[wrp*5+3]=k3; sred[wrp*5+4]=wt;
            }
            __syncthreads();
            if (t < 5) {
                float s = 0.f;
                for (int ww = 0; ww < 16; ww++) s += sred[ww*5+t];
                if (t < 4) sSk[nn][t] = s; else sWtot[nn] = s;
            }
            __syncthreads();
        }
    }

    // --- Phase C: coalesced k-split accumulation, 4 quarters of i ---
    {
        int r = t & 127;
        int q = t >> 7;                 // 0..3
        float acc[TN];
        #pragma unroll
        for (int nn = 0; nn < TN; nn++) acc[nn] = 0.f;
        int i0 = q * 96;
        #pragma unroll 2
        for (int i = i0; i < i0 + 96; i++) {
            #pragma unroll
            for (int nn = 0; nn < TN; nn++) {
                int kh = skh[nn][i];
                float c = scoef[nn][i];
                if (kh >= 0 && c != 0.f) {
                    float pv = g_Pk[kh*(NN*RR) + i*RR + r];
                    acc[nn] += c * fmaxf(sPn[(nn*KK + kh)*RR + r] - pv
                                         + sbk[kh*RR + r], 0.f);
                }
            }
        }
        if (q) {
            #pragma unroll
            for (int nn = 0; nn < TN; nn++) sCpart[q-1][nn][r] = acc[nn];
        }
        __syncthreads();
        if (q == 0) {
            float wm0 = W_mode[r*4+0], wm1 = W_mode[r*4+1];
            float wm2 = W_mode[r*4+2], wm3 = W_mode[r*4+3];
            float bm = b_mode[r];
            const float* wi = W_in + r*4;
            float wi0 = wi[0], wi1 = wi[1], wi2 = wi[2], wi3 = wi[3];
            float bi = b_in[r];
            #pragma unroll
            for (int nn = 0; nn < TN; nn++) {
                float a = acc[nn] + sCpart[0][nn][r] + sCpart[1][nn][r]
                        + sCpart[2][nn][r];
                float soc = a + sSk[nn][0]*wm0 + sSk[nn][1]*wm1
                              + sSk[nn][2]*wm2 + sSk[nn][3]*wm3
                              + sWtot[nn]*bm;
                float xr = fmaxf(wi0*snd[nn][0] + wi1*snd[nn][1]
                               + wi2*snd[nn][2] + wi3*snd[nn][3] + bi, 0.f)
                         + soc;
                g_X[(n0+nn)*RR + r] = xr;
            }
        }
    }
}

// ---------------------------------------------------------------------------
// K3a: gates GEMM, W tile staged in smem. grid (16 j-tiles, 24 node-tiles).
// ---------------------------------------------------------------------------
__global__ void __launch_bounds__(256) k_gates(
    const float* __restrict__ h_in,
    const float* __restrict__ b_ih, const float* __restrict__ b_hh)
{
    int jt = blockIdx.x;   // 0..15
    int mt = blockIdx.y;   // 0..23
    int t = threadIdx.x;

    __shared__ float sW[256*32];   // [k][jl]
    __shared__ float sA[16*256];   // [n][k]

    for (int e = t; e < 256*32; e += 256) {
        int k = e >> 5, jl = e & 31;
        sW[e] = g_WT[k*JJ + jt*32 + jl];
    }
    for (int e = t; e < 16*256; e += 256) {
        int n = e >> 8, k = e & 255;
        sA[e] = (k < 128) ? g_X[(mt*16+n)*RR + k]
                          : h_in[(mt*16+n)*RR + (k-128)];
    }
    __syncthreads();

    int jl = t & 31, g = t >> 5;      // g: 0..7 -> nodes 2g, 2g+1
    int na = g*2;
    const float* A0 = sA + na*256;
    const float* A1 = sA + (na+1)*256;
    float acc0 = 0.f, acc1 = 0.f;
    #pragma unroll 8
    for (int k = 0; k < 256; k++) {
        float w = sW[k*32 + jl];
        acc0 = fmaf(A0[k], w, acc0);
        acc1 = fmaf(A1[k], w, acc1);
    }
    int j = jt*32 + jl;
    float bb = b_ih[j] + b_hh[j];
    g_G[(mt*16+na)*JJ + j]   = acc0 + bb;
    g_G[(mt*16+na+1)*JJ + j] = acc1 + bb;
}

// ---------------------------------------------------------------------------
// K3b: LSTM pointwise combine + MDN heads. 8 nodes/block, 48 blocks.
// ---------------------------------------------------------------------------
__device__ __forceinline__ float sigf(float x) { return 1.f / (1.f + __expf(-x)); }

#define BN 8
__global__ void __launch_bounds__(256) k_comb(
    const float* __restrict__ c_in,
    const float* __restrict__ W_pi, const float* __restrict__ b_pi,
    const float* __restrict__ W_mu, const float* __restrict__ b_mu,
    const float* __restrict__ W_sig, const float* __restrict__ b_sig,
    float* __restrict__ out)
{
    int n0 = blockIdx.x * BN;
    int t = threadIdx.x;

    __shared__ float sW[25*RR];
    __shared__ float sh[BN][RR];
    __shared__ float sLg[BN][25];

    for (int e = t; e < 25*RR; e += 256) {
        float v = (e < 640) ? W_pi[e] : (e < 1920) ? W_mu[e-640] : W_sig[e-1920];
        sW[e] = v;
    }

    for (int e = t; e < BN*RR; e += 256) {
        int nn = e >> 7, r = e & 127;
        int n = n0 + nn;
        float gi = g_G[n*JJ + r];
        float gf = g_G[n*JJ + RR + r];
        float gg = g_G[n*JJ + 2*RR + r];
        float go = g_G[n*JJ + 3*RR + r];
        float cp = c_in[n*RR + r];
        float c = sigf(gf)*cp + sigf(gi)*tanhf(gg);
        float h = sigf(go)*tanhf(c);
        out[C_OFF + n*RR + r] = c;
        out[H_OFF + n*RR + r] = h;
        sh[nn][r] = h;
    }
    __syncthreads();

    if (t < BN*25) {
        int nn = t / 25, q = t % 25;
        const float* wr = sW + q*RR;
        float acc = 0.f;
        #pragma unroll 4
        for (int r = 0; r < RR; r++) acc += wr[r] * sh[nn][r];
        sLg[nn][q] = acc;
    }
    __syncthreads();

    if (t < BN) {  // pi softmax
        int nn = t;
        float l[GG];
        float m = -3.0e38f;
        #pragma unroll
        for (int g = 0; g < GG; g++) { l[g] = sLg[nn][g] + b_pi[g]; m = fmaxf(m, l[g]); }
        float s = 0.f;
        #pragma unroll
        for (int g = 0; g < GG; g++) { l[g] = __expf(l[g] - m); s += l[g]; }
        float inv = 1.f / s;
        #pragma unroll
        for (int g = 0; g < GG; g++)
            out[PI_OFF + (n0+nn)*GG + g] = l[g] * inv;
    }
    if (t >= 32 && t < 32 + BN*10) {  // mu
        int idx = t - 32;
        int nn = idx / 10, q = idx % 10;
        out[MU_OFF + (n0+nn)*10 + q] = sLg[nn][5+q] + b_mu[q];
    }
    if (t >= 128 && t < 128 + BN*10) {  // sigma
        int idx = t - 128;
        int nn = idx / 10, q = idx % 10;
        out[SIG_OFF + (n0+nn)*10 + q] = __expf(sLg[nn][15+q] + b_sig[q]);
    }
}

// ---------------------------------------------------------------------------
extern "C" void kernel_launch(void* const* d_in, const int* in_sizes, int n_in,
                              void* d_out, int out_size)
{
    const float* nodes   = (const float*)d_in[0];
    const int*   visible = (const int*)  d_in[1];
    const float* h_in    = (const float*)d_in[2];
    const float* c_in    = (const float*)d_in[3];
    const float* W_loc   = (const float*)d_in[4];
    const float* b_loc   = (const float*)d_in[5];
    const float* W_score = (const float*)d_in[6];
    const float* b_score = (const float*)d_in[7];
    const float* W_mode  = (const float*)d_in[8];
    const float* b_mode  = (const float*)d_in[9];
    const float* W_in    = (const float*)d_in[10];
    const float* b_in    = (const float*)d_in[11];
    const float* W_ih    = (const float*)d_in[12];
    const float* W_hh    = (const float*)d_in[13];
    const float* b_ih    = (const float*)d_in[14];
    const float* b_hh    = (const float*)d_in[15];
    const float* W_pi    = (const float*)d_in[16];
    const float* b_pi    = (const float*)d_in[17];
    const float* W_mu    = (const float*)d_in[18];
    const float* b_mu    = (const float*)d_in[19];
    const float* W_sig   = (const float*)d_in[20];
    const float* b_sig   = (const float*)d_in[21];
    float* out = (float*)d_out;

    k_pre<<<NN/8, 512>>>(nodes, W_loc, W_mode, b_mode);
    dim3 wt_grid(16, 4, 2);
    k_wt<<<wt_grid, 256>>>(W_ih, W_hh);
    dim3 a_grid(NN/TN, 4);
    k_socialA<<<a_grid, 256>>>(visible, h_in, b_loc, W_score, b_score);
    k_socialBC<<<NN/TN, 512>>>(nodes, b_loc, W_mode, b_mode, W_in, b_in);
    dim3 g_grid(16, 24);
    k_gates<<<g_grid, 256>>>(h_in, b_ih, b_hh);
    k_comb<<<NN/BN, 256>>>(c_in, W_pi, b_pi, W_mu, b_mu, W_sig, b_sig, out);
}

// round 12
// speedup vs baseline: 2.2057x; 1.4628x over previous
#include <cuda_runtime.h>
#include <math.h>

#define NN 384
#define RR 128
#define KK 4
#define JJ 512   // K*R
#define GG 5
#define OO 2
#define TN 3     // nodes per social tile

#define PI_OFF  0
#define MU_OFF  (NN*GG)              // 1920
#define SIG_OFF (MU_OFF + NN*GG*OO)  // 5760
#define H_OFF   (SIG_OFF + NN*GG*OO) // 9600
#define C_OFF   (H_OFF + NN*RR)      // 58752

// Scratch (no allocations allowed)
__device__ float g_Pj[NN*JJ];       // interleaved: P[m][j],  j = r*4+k
__device__ float g_Pk[KK*NN*RR];    // k-split:     P[k][m][r]
__device__ float g_X[NN*RR];        // bias/mode part of x (C partials added later)
__device__ float g_Cp[4*NN*RR];     // Phase-C partials per i-quarter
__device__ float g_WT[(256+8)*JJ];  // transposed [X|H] weights
__device__ float g_G[NN*JJ];        // gate pre-activations
__device__ float g_sv[NN*NN];       // phase-A outputs
__device__ float g_al[NN*NN];
__device__ int   g_kh[NN*NN];
__device__ float g_coef[NN*NN];     // phase-B coefficients
__device__ float g_Wmsum[KK];
__device__ float g_bmsum[1];

// ---------------------------------------------------------------------------
// K1: P in both layouts. 2 nodes per block (192 blocks).
// ---------------------------------------------------------------------------
__global__ void __launch_bounds__(512) k_pre(
    const float* __restrict__ nodes, const float* __restrict__ W_loc,
    const float* __restrict__ W_mode, const float* __restrict__ b_mode)
{
    int j = threadIdx.x;            // W_loc row j ; r = j>>2, k = j&3
    int m0 = blockIdx.x * 2;
    __shared__ float nd[2][6];
    if (j < 12) nd[j/6][j%6] = nodes[m0*6 + j];
    const float* w = W_loc + j*6;
    float w0 = w[0], w1 = w[1], w2 = w[2], w3 = w[3], w4 = w[4], w5 = w[5];
    int k = j & 3, r = j >> 2;
    __syncthreads();
    #pragma unroll
    for (int mm = 0; mm < 2; mm++) {
        float v = w0*nd[mm][0] + w1*nd[mm][1] + w2*nd[mm][2]
                + w3*nd[mm][3] + w4*nd[mm][4] + w5*nd[mm][5];
        g_Pj[(m0+mm)*JJ + j] = v;
        g_Pk[k*(NN*RR) + (m0+mm)*RR + r] = v;
    }

    if (blockIdx.x == 0 && j < 32) {
        float sk0=0.f, sk1=0.f, sk2=0.f, sk3=0.f, sbm=0.f;
        for (int rr = j; rr < RR; rr += 32) {
            sk0 += W_mode[rr*4+0];
            sk1 += W_mode[rr*4+1];
            sk2 += W_mode[rr*4+2];
            sk3 += W_mode[rr*4+3];
            sbm += b_mode[rr];
        }
        #pragma unroll
        for (int o = 16; o > 0; o >>= 1) {
            sk0 += __shfl_down_sync(0xffffffffu, sk0, o);
            sk1 += __shfl_down_sync(0xffffffffu, sk1, o);
            sk2 += __shfl_down_sync(0xffffffffu, sk2, o);
            sk3 += __shfl_down_sync(0xffffffffu, sk3, o);
            sbm += __shfl_down_sync(0xffffffffu, sbm, o);
        }
        if (j == 0) {
            g_Wmsum[0] = sk0; g_Wmsum[1] = sk1;
            g_Wmsum[2] = sk2; g_Wmsum[3] = sk3;
            g_bmsum[0] = sbm;
        }
    }
}

// ---------------------------------------------------------------------------
// K1b: transpose W_ih / W_hh into g_WT[k][j].
// ---------------------------------------------------------------------------
__global__ void __launch_bounds__(256) k_wt(
    const float* __restrict__ W_ih, const float* __restrict__ W_hh)
{
    __shared__ float tile[32][33];
    int jb = blockIdx.x * 32;          // gridDim.x = 16
    int rb = blockIdx.y * 32;          // gridDim.y = 4
    const float* W = blockIdx.z ? W_hh : W_ih;
    int tx = threadIdx.x & 31;
    int ty = threadIdx.x >> 5;
    #pragma unroll
    for (int u = 0; u < 32; u += 8)
        tile[ty+u][tx] = W[(jb+ty+u)*RR + rb + tx];
    __syncthreads();
    int kbase = rb + blockIdx.z * RR;
    #pragma unroll
    for (int u = 0; u < 32; u += 8)
        g_WT[(kbase+ty+u)*JJ + jb + tx] = tile[tx][ty+u];
}

// ---------------------------------------------------------------------------
// K2a: Phase A — grid (128 n-tiles, 12 i-tiles), 256 thr, one pass.
// ---------------------------------------------------------------------------
__global__ void __launch_bounds__(256) k_socialA(
    const int* __restrict__ visible, const float* __restrict__ h_in,
    const float* __restrict__ b_loc, const float* __restrict__ W_score,
    const float* __restrict__ b_score)
{
    int n0 = blockIdx.x * TN;
    int ib = blockIdx.y * 32;
    int t = threadIdx.x;
    int lane = t & 31;
    int wrp  = t >> 5;

    __shared__ __align__(16) float sPn[TN*JJ];
    __shared__ __align__(16) float sb[JJ];
    __shared__ float shs[TN*RR];
    __shared__ float sscal[8];

    for (int e = t; e < TN*JJ; e += 256) sPn[e] = g_Pj[n0*JJ + e];
    for (int e = t; e < JJ; e += 256)    sb[e] = b_loc[e];
    for (int e = t; e < TN*RR; e += 256)
        shs[e] = h_in[n0*RR + e] * W_score[e & 127];
    if (t == 0) sscal[0] = b_score[0];
    if (t >= 32 && t < 36) sscal[1 + (t-32)] = g_Wmsum[t-32];
    if (t == 36) sscal[5] = g_bmsum[0];
    __syncthreads();

    int p   = lane >> 3;   // pair within warp (0..3)
    int sub = lane & 7;    // lane within pair
    const float4* B4 = (const float4*)sb;
    int i = ib + wrp*4 + p;
    const float4* Pi = (const float4*)(g_Pj + i*JJ);
    float s[TN][4], L[TN][4];
    #pragma unroll
    for (int nn = 0; nn < TN; nn++)
        #pragma unroll
        for (int kk = 0; kk < 4; kk++) { s[nn][kk] = 0.f; L[nn][kk] = 0.f; }

    #pragma unroll
    for (int u = 0; u < 16; u++) {
        int r = sub + 8*u;
        float4 pi4 = Pi[r];
        float4 b4  = B4[r];
        float bx = b4.x - pi4.x;
        float by = b4.y - pi4.y;
        float bz = b4.z - pi4.z;
        float bw = b4.w - pi4.w;
        #pragma unroll
        for (int nn = 0; nn < TN; nn++) {
            float4 pn4 = ((const float4*)(sPn + nn*JJ))[r];
            float hv = shs[nn*RR + r];
            float l0 = fmaxf(pn4.x + bx, 0.f);
            float l1 = fmaxf(pn4.y + by, 0.f);
            float l2 = fmaxf(pn4.z + bz, 0.f);
            float l3 = fmaxf(pn4.w + bw, 0.f);
            s[nn][0] += l0*hv; s[nn][1] += l1*hv;
            s[nn][2] += l2*hv; s[nn][3] += l3*hv;
            L[nn][0] += l0; L[nn][1] += l1;
            L[nn][2] += l2; L[nn][3] += l3;
        }
    }
    #pragma unroll
    for (int o = 4; o > 0; o >>= 1) {
        #pragma unroll
        for (int nn = 0; nn < TN; nn++)
            #pragma unroll
            for (int kk = 0; kk < 4; kk++) {
                s[nn][kk] += __shfl_xor_sync(0xffffffffu, s[nn][kk], o);
                L[nn][kk] += __shfl_xor_sync(0xffffffffu, L[nn][kk], o);
            }
    }
    if (sub == 0) {
        float bs = sscal[0];
        #pragma unroll
        for (int nn = 0; nn < TN; nn++) {
            float s0 = s[nn][0]+bs, s1 = s[nn][1]+bs;
            float s2 = s[nn][2]+bs, s3 = s[nn][3]+bs;
            int kh = 0; float smx = s0;
            if (s1 > smx) { smx = s1; kh = 1; }
            if (s2 > smx) { smx = s2; kh = 2; }
            if (s3 > smx) { smx = s3; kh = 3; }
            float e0 = __expf(s0 - smx), e1 = __expf(s1 - smx);
            float e2 = __expf(s2 - smx), e3 = __expf(s3 - smx);
            float soft = 1.0f / (e0 + e1 + e2 + e3);   // softmax @khat
            float alpha = (1.0f - soft) + soft;        // straight-through
            float Lh = (kh==0) ? L[nn][0] : (kh==1) ? L[nn][1]
                     : (kh==2) ? L[nn][2] : L[nn][3];
            float sv = alpha*Lh + (alpha*sscal[1+kh] + sscal[5]);
            int vis = visible[(n0+nn)*NN + i];
            int idx = (n0+nn)*NN + i;
            g_kh[idx] = (vis > 0) ? kh : -1;
            g_al[idx] = alpha;
            g_sv[idx] = sv;
        }
    }
}

// ---------------------------------------------------------------------------
// K2b: Phase B — per-node masked softmax (384 blocks, 128 thr).
// Writes g_coef and the bias/mode part of x into g_X.
// ---------------------------------------------------------------------------
__global__ void __launch_bounds__(128) k_socialB(
    const float* __restrict__ nodes,
    const float* __restrict__ W_mode, const float* __restrict__ b_mode,
    const float* __restrict__ W_in,   const float* __restrict__ b_in)
{
    int n = blockIdx.x;
    int t = threadIdx.x;
    int lane = t & 31;
    int wrp  = t >> 5;   // 0..3

    __shared__ float ssv[NN];
    __shared__ float sal[NN];
    __shared__ int   skh[NN];
    __shared__ float sred[4*5];
    __shared__ float sm4[KK], sden[KK], sSk[KK];
    __shared__ float sWtot;
    __shared__ float snd4[4];

    for (int e = t; e < NN; e += 128) {
        ssv[e] = g_sv[n*NN + e];
        sal[e] = g_al[n*NN + e];
        skh[e] = g_kh[n*NN + e];
    }
    if (t < 4) snd4[t] = nodes[n*6 + t];
    __syncthreads();

    {   // pass 1: max per head
        float m0=-3.0e38f, m1=-3.0e38f, m2=-3.0e38f, m3=-3.0e38f;
        for (int i = t; i < NN; i += 128) {
            int kh = skh[i];
            float v = ssv[i];
            if (kh == 0) m0 = fmaxf(m0, v);
            else if (kh == 1) m1 = fmaxf(m1, v);
            else if (kh == 2) m2 = fmaxf(m2, v);
            else if (kh == 3) m3 = fmaxf(m3, v);
        }
        #pragma unroll
        for (int o = 16; o > 0; o >>= 1) {
            m0 = fmaxf(m0, __shfl_xor_sync(0xffffffffu, m0, o));
            m1 = fmaxf(m1, __shfl_xor_sync(0xffffffffu, m1, o));
            m2 = fmaxf(m2, __shfl_xor_sync(0xffffffffu, m2, o));
            m3 = fmaxf(m3, __shfl_xor_sync(0xffffffffu, m3, o));
        }
        if (lane == 0) {
            sred[wrp*4+0]=m0; sred[wrp*4+1]=m1;
            sred[wrp*4+2]=m2; sred[wrp*4+3]=m3;
        }
        __syncthreads();
        if (t < 4) {
            float m = sred[t];
            for (int ww = 1; ww < 4; ww++) m = fmaxf(m, sred[ww*4+t]);
            sm4[t] = m;
        }
        __syncthreads();
    }
    {   // pass 2: denominators
        float d0=0.f, d1=0.f, d2=0.f, d3=0.f;
        for (int i = t; i < NN; i += 128) {
            int kh = skh[i];
            if (kh >= 0) {
                float e = __expf(ssv[i] - sm4[kh]);
                if (kh == 0) d0 += e;
                else if (kh == 1) d1 += e;
                else if (kh == 2) d2 += e;
                else d3 += e;
            }
        }
        #pragma unroll
        for (int o = 16; o > 0; o >>= 1) {
            d0 += __shfl_xor_sync(0xffffffffu, d0, o);
            d1 += __shfl_xor_sync(0xffffffffu, d1, o);
            d2 += __shfl_xor_sync(0xffffffffu, d2, o);
            d3 += __shfl_xor_sync(0xffffffffu, d3, o);
        }
        if (lane == 0) {
            sred[wrp*4+0]=d0; sred[wrp*4+1]=d1;
            sred[wrp*4+2]=d2; sred[wrp*4+3]=d3;
        }
        __syncthreads();
        if (t < 4) {
            float d = 0.f;
            for (int ww = 0; ww < 4; ww++) d += sred[ww*4+t];
            sden[t] = d;
        }
        __syncthreads();
    }
    {   // pass 3: coefficients + group sums
        float k0=0.f, k1=0.f, k2=0.f, k3=0.f, wt=0.f;
        for (int i = t; i < NN; i += 128) {
            int kh = skh[i];
            float c = 0.f;
            if (kh >= 0) {
                float wv = __expf(ssv[i] - sm4[kh]) / sden[kh];
                c = wv * sal[i];
                wt += wv;
                if (kh == 0) k0 += c;
                else if (kh == 1) k1 += c;
                else if (kh == 2) k2 += c;
                else k3 += c;
            }
            g_coef[n*NN + i] = c;
        }
        #pragma unroll
        for (int o = 16; o > 0; o >>= 1) {
            k0 += __shfl_xor_sync(0xffffffffu, k0, o);
            k1 += __shfl_xor_sync(0xffffffffu, k1, o);
            k2 += __shfl_xor_sync(0xffffffffu, k2, o);
            k3 += __shfl_xor_sync(0xffffffffu, k3, o);
            wt += __shfl_xor_sync(0xffffffffu, wt, o);
        }
        if (lane == 0) {
            sred[wrp*5+0]=k0; sred[wrp*5+1]=k1; sred[wrp*5+2]=k2;
            sred[wrp*5+3]=k3; sred[wrp*5+4]=wt;
        }
        __syncthreads();
        if (t < 5) {
            float s = 0.f;
            for (int ww = 0; ww < 4; ww++) s += sred[ww*5+t];
            if (t < 4) sSk[t] = s; else sWtot = s;
        }
        __syncthreads();
    }

    // base x (everything except the Phase-C accumulation)
    {
        int r = t;
        float base = sSk[0]*W_mode[r*4+0] + sSk[1]*W_mode[r*4+1]
                   + sSk[2]*W_mode[r*4+2] + sSk[3]*W_mode[r*4+3]
                   + sWtot * b_mode[r];
        const float* wi = W_in + r*4;
        float xr = fmaxf(wi[0]*snd4[0] + wi[1]*snd4[1]
                       + wi[2]*snd4[2] + wi[3]*snd4[3] + b_in[r], 0.f) + base;
        g_X[n*RR + r] = xr;
    }
}

// ---------------------------------------------------------------------------
// K2c: Phase C — grid (128 n-tiles, 4 i-quarters), 256 thr. Writes partials.
// ---------------------------------------------------------------------------
__global__ void __launch_bounds__(256) k_socialC(
    const float* __restrict__ b_loc)
{
    int n0 = blockIdx.x * TN;
    int iq = blockIdx.y;
    int i0 = iq * 96;
    int t = threadIdx.x;

    __shared__ __align__(16) float sPn[TN*KK*RR];
    __shared__ __align__(16) float sbk[KK*RR];
    __shared__ float scf[TN][96];
    __shared__ int   skh[TN][96];
    __shared__ float spart[TN][RR];

    for (int e = t; e < TN*KK*RR; e += 256) {
        int nn = e >> 9, k = (e >> 7) & 3, r = e & 127;
        sPn[e] = g_Pk[k*(NN*RR) + (n0+nn)*RR + r];
    }
    for (int e = t; e < KK*RR; e += 256) {
        int k = e >> 7, r = e & 127;
        sbk[e] = b_loc[r*4 + k];
    }
    for (int e = t; e < TN*96; e += 256) {
        int nn = e / 96, i = e % 96;
        scf[nn][i] = g_coef[(n0+nn)*NN + i0 + i];
        skh[nn][i] = g_kh[(n0+nn)*NN + i0 + i];
    }
    __syncthreads();

    int r = t & 127;
    int h2 = t >> 7;
    float acc[TN];
    #pragma unroll
    for (int nn = 0; nn < TN; nn++) acc[nn] = 0.f;
    int ia = h2 * 48;
    #pragma unroll 2
    for (int ii = ia; ii < ia + 48; ii++) {
        #pragma unroll
        for (int nn = 0; nn < TN; nn++) {
            int kh = skh[nn][ii];
            float c = scf[nn][ii];
            if (kh >= 0 && c != 0.f) {
                float pv = g_Pk[kh*(NN*RR) + (i0+ii)*RR + r];
                acc[nn] += c * fmaxf(sPn[(nn*KK + kh)*RR + r] - pv
                                     + sbk[kh*RR + r], 0.f);
            }
        }
    }
    if (h2) {
        #pragma unroll
        for (int nn = 0; nn < TN; nn++) spart[nn][r] = acc[nn];
    }
    __syncthreads();
    if (!h2) {
        #pragma unroll
        for (int nn = 0; nn < TN; nn++)
            g_Cp[iq*(NN*RR) + (n0+nn)*RR + r] = acc[nn] + spart[nn][r];
    }
}

// ---------------------------------------------------------------------------
// K3a: gates GEMM, W tile in smem. grid (16 j-tiles, 24 node-tiles).
// Also folds the 4 Phase-C partials into the X input.
// ---------------------------------------------------------------------------
__global__ void __launch_bounds__(256) k_gates(
    const float* __restrict__ h_in,
    const float* __restrict__ b_ih, const float* __restrict__ b_hh)
{
    int jt = blockIdx.x;   // 0..15
    int mt = blockIdx.y;   // 0..23
    int t = threadIdx.x;

    __shared__ __align__(16) float sW[256*32];   // [k][jl]
    __shared__ __align__(16) float sA[16*256];   // [n][k]

    for (int e = t; e < 256*32; e += 256) {
        int k = e >> 5, jl = e & 31;
        sW[e] = g_WT[k*JJ + jt*32 + jl];
    }
    for (int e = t; e < 16*256; e += 256) {
        int n = e >> 8, k = e & 255;
        int gn = mt*16 + n;
        float v;
        if (k < 128) {
            v = g_X[gn*RR + k]
              + g_Cp[0*(NN*RR) + gn*RR + k] + g_Cp[1*(NN*RR) + gn*RR + k]
              + g_Cp[2*(NN*RR) + gn*RR + k] + g_Cp[3*(NN*RR) + gn*RR + k];
        } else {
            v = h_in[gn*RR + (k-128)];
        }
        sA[e] = v;
    }
    __syncthreads();

    int jl = t & 31, g = t >> 5;      // g: 0..7 -> nodes 2g, 2g+1
    int na = g*2;
    const float* A0 = sA + na*256;
    const float* A1 = sA + (na+1)*256;
    float acc0 = 0.f, acc1 = 0.f;
    #pragma unroll 4
    for (int k = 0; k < 256; k += 4) {
        float4 a0 = *(const float4*)&A0[k];
        float4 a1 = *(const float4*)&A1[k];
        float w0 = sW[(k+0)*32 + jl];
        float w1 = sW[(k+1)*32 + jl];
        float w2 = sW[(k+2)*32 + jl];
        float w3 = sW[(k+3)*32 + jl];
        acc0 += a0.x*w0 + a0.y*w1 + a0.z*w2 + a0.w*w3;
        acc1 += a1.x*w0 + a1.y*w1 + a1.z*w2 + a1.w*w3;
    }
    int j = jt*32 + jl;
    float bb = b_ih[j] + b_hh[j];
    g_G[(mt*16+na)*JJ + j]   = acc0 + bb;
    g_G[(mt*16+na+1)*JJ + j] = acc1 + bb;
}

// ---------------------------------------------------------------------------
// K3b: LSTM pointwise combine + MDN heads. 8 nodes/block, 48 blocks.
// ---------------------------------------------------------------------------
__device__ __forceinline__ float sigf(float x) { return 1.f / (1.f + __expf(-x)); }

#define BN 8
__global__ void __launch_bounds__(256) k_comb(
    const float* __restrict__ c_in,
    const float* __restrict__ W_pi, const float* __restrict__ b_pi,
    const float* __restrict__ W_mu, const float* __restrict__ b_mu,
    const float* __restrict__ W_sig, const float* __restrict__ b_sig,
    float* __restrict__ out)
{
    int n0 = blockIdx.x * BN;
    int t = threadIdx.x;

    __shared__ float sW[25*RR];
    __shared__ float sh[BN][RR];
    __shared__ float sLg[BN][25];

    for (int e = t; e < 25*RR; e += 256) {
        float v = (e < 640) ? W_pi[e] : (e < 1920) ? W_mu[e-640] : W_sig[e-1920];
        sW[e] = v;
    }

    for (int e = t; e < BN*RR; e += 256) {
        int nn = e >> 7, r = e & 127;
        int n = n0 + nn;
        float gi = g_G[n*JJ + r];
        float gf = g_G[n*JJ + RR + r];
        float gg = g_G[n*JJ + 2*RR + r];
        float go = g_G[n*JJ + 3*RR + r];
        float cp = c_in[n*RR + r];
        float c = sigf(gf)*cp + sigf(gi)*tanhf(gg);
        float h = sigf(go)*tanhf(c);
        out[C_OFF + n*RR + r] = c;
        out[H_OFF + n*RR + r] = h;
        sh[nn][r] = h;
    }
    __syncthreads();

    if (t < BN*25) {
        int nn = t / 25, q = t % 25;
        const float* wr = sW + q*RR;
        float acc = 0.f;
        #pragma unroll 4
        for (int r = 0; r < RR; r++) acc += wr[r] * sh[nn][r];
        sLg[nn][q] = acc;
    }
    __syncthreads();

    if (t < BN) {  // pi softmax
        int nn = t;
        float l[GG];
        float m = -3.0e38f;
        #pragma unroll
        for (int g = 0; g < GG; g++) { l[g] = sLg[nn][g] + b_pi[g]; m = fmaxf(m, l[g]); }
        float s = 0.f;
        #pragma unroll
        for (int g = 0; g < GG; g++) { l[g] = __expf(l[g] - m); s += l[g]; }
        float inv = 1.f / s;
        #pragma unroll
        for (int g = 0; g < GG; g++)
            out[PI_OFF + (n0+nn)*GG + g] = l[g] * inv;
    }
    if (t >= 32 && t < 32 + BN*10) {  // mu
        int idx = t - 32;
        int nn = idx / 10, q = idx % 10;
        out[MU_OFF + (n0+nn)*10 + q] = sLg[nn][5+q] + b_mu[q];
    }
    if (t >= 128 && t < 128 + BN*10) {  // sigma
        int idx = t - 128;
        int nn = idx / 10, q = idx % 10;
        out[SIG_OFF + (n0+nn)*10 + q] = __expf(sLg[nn][15+q] + b_sig[q]);
    }
}

// ---------------------------------------------------------------------------
extern "C" void kernel_launch(void* const* d_in, const int* in_sizes, int n_in,
                              void* d_out, int out_size)
{
    const float* nodes   = (const float*)d_in[0];
    const int*   visible = (const int*)  d_in[1];
    const float* h_in    = (const float*)d_in[2];
    const float* c_in    = (const float*)d_in[3];
    const float* W_loc   = (const float*)d_in[4];
    const float* b_loc   = (const float*)d_in[5];
    const float* W_score = (const float*)d_in[6];
    const float* b_score = (const float*)d_in[7];
    const float* W_mode  = (const float*)d_in[8];
    const float* b_mode  = (const float*)d_in[9];
    const float* W_in    = (const float*)d_in[10];
    const float* b_in    = (const float*)d_in[11];
    const float* W_ih    = (const float*)d_in[12];
    const float* W_hh    = (const float*)d_in[13];
    const float* b_ih    = (const float*)d_in[14];
    const float* b_hh    = (const float*)d_in[15];
    const float* W_pi    = (const float*)d_in[16];
    const float* b_pi    = (const float*)d_in[17];
    const float* W_mu    = (const float*)d_in[18];
    const float* b_mu    = (const float*)d_in[19];
    const float* W_sig   = (const float*)d_in[20];
    const float* b_sig   = (const float*)d_in[21];
    float* out = (float*)d_out;

    k_pre<<<NN/2, 512>>>(nodes, W_loc, W_mode, b_mode);
    dim3 wt_grid(16, 4, 2);
    k_wt<<<wt_grid, 256>>>(W_ih, W_hh);
    dim3 a_grid(NN/TN, 12);
    k_socialA<<<a_grid, 256>>>(visible, h_in, b_loc, W_score, b_score);
    k_socialB<<<NN, 128>>>(nodes, W_mode, b_mode, W_in, b_in);
    dim3 c_grid(NN/TN, 4);
    k_socialC<<<c_grid, 256>>>(b_loc);
    dim3 g_grid(16, 24);
    k_gates<<<g_grid, 256>>>(h_in, b_ih, b_hh);
    k_comb<<<NN/BN, 256>>>(c_in, W_pi, b_pi, W_mu, b_mu, W_sig, b_sig, out);
}